// round 1
// baseline (speedup 1.0000x reference)
#include <cuda_runtime.h>
#include <cstdint>
#include <math.h>

// Problem constants
#define HS    4096     // hidden size
#define NHEADS 32
#define NKV    8
#define HD     128
#define SEQ    4096
#define BATCH  2
#define MTOT   (BATCH * SEQ)   // 8192 rows

// ---------------- scratch (device globals: no allocs allowed) ----------------
__device__ float g_Q[(size_t)MTOT * HS];          // 134 MB
__device__ float g_K[(size_t)MTOT * NKV * HD];    // 33.5 MB
__device__ float g_V[(size_t)MTOT * NKV * HD];    // 33.5 MB
__device__ float g_Y[(size_t)MTOT * HS];          // 134 MB
__device__ float g_sin[SEQ * 64];
__device__ float g_cos[SEQ * 64];

// ---------------- RoPE sin/cos table --------------------------------------
// Reference: emb = 10000 ** (2*floor(i/2)/64)  (fp32), freq = pos * emb (fp32),
// sin/cos of fp32 freq. freq reaches ~3e7, so the *bits* of emb matter.
// Compute pow in double (matches libdevice's double-path powf; fast-math immune),
// single fp32 multiply for freq (same rounding as jax), trig in double.
__global__ void rope_table_kernel() {
    int pos = blockIdx.x;
    int d   = threadIdx.x;            // 0..63
    int k2  = d & ~1;                 // 2*floor(d/2)
    float e = (float)k2 / 64.0f;      // exact in fp32
    float emb  = (float)pow(10000.0, (double)e);
    float freq = (float)pos * emb;    // single fp32 rounding, like jax
    double fd = (double)freq;
    g_sin[pos * 64 + d] = (float)sin(fd);
    g_cos[pos * 64 + d] = (float)cos(fd);
}

// ---------------- TF32 GEMM: C[M,N] = A[M,K] @ B[K,N], all row-major -------
#define BM 128
#define BN 128
#define BK 32

__device__ __forceinline__ uint32_t f2tf32(float x) {
    uint32_t u;
    asm("cvt.rna.tf32.f32 %0, %1;" : "=r"(u) : "f"(x));
    return u;
}

__device__ __forceinline__ void mma1688(float c[4],
                                        uint32_t a0, uint32_t a1, uint32_t a2, uint32_t a3,
                                        uint32_t b0, uint32_t b1) {
    asm("mma.sync.aligned.m16n8k8.row.col.f32.tf32.tf32.f32 "
        "{%0,%1,%2,%3}, {%4,%5,%6,%7}, {%8,%9}, {%0,%1,%2,%3};"
        : "+f"(c[0]), "+f"(c[1]), "+f"(c[2]), "+f"(c[3])
        : "r"(a0), "r"(a1), "r"(a2), "r"(a3), "r"(b0), "r"(b1));
}

__global__ __launch_bounds__(256, 2)
void gemm_tf32(const float* __restrict__ A, const float* __restrict__ B,
               float* __restrict__ C, int M, int N, int K)
{
    __shared__ float As[BM][BK + 4];   // bank map 4g+tg: conflict-free frag loads
    __shared__ float Bs[BK][BN + 8];   // bank map 8tg+g: conflict-free frag loads

    const int tid  = threadIdx.x;
    const int lane = tid & 31, warp = tid >> 5;
    const int warpM = warp & 1;        // 0..1 -> 64-row slab
    const int warpN = warp >> 1;       // 0..3 -> 32-col slab
    const int g  = lane >> 2;          // groupID
    const int tg = lane & 3;           // threadID_in_group

    const int rowBase = blockIdx.y * BM;
    const int colBase = blockIdx.x * BN;

    float c[4][4][4];
    #pragma unroll
    for (int mt = 0; mt < 4; mt++)
        #pragma unroll
        for (int nt = 0; nt < 4; nt++)
            #pragma unroll
            for (int i = 0; i < 4; i++) c[mt][nt][i] = 0.f;

    const int arow = tid >> 3;           // 0..31
    const int acol = (tid & 7) * 4;      // 0..28
    const int brow = tid >> 5;           // 0..7
    const int bcol = (lane) * 4;         // 0..124

    for (int kt = 0; kt < K; kt += BK) {
        // global -> smem (tf32-round once at store)
        #pragma unroll
        for (int p = 0; p < 4; p++) {
            int r = arow + p * 32;
            float4 v = *reinterpret_cast<const float4*>(
                A + (size_t)(rowBase + r) * K + kt + acol);
            float4 t;
            t.x = __uint_as_float(f2tf32(v.x));
            t.y = __uint_as_float(f2tf32(v.y));
            t.z = __uint_as_float(f2tf32(v.z));
            t.w = __uint_as_float(f2tf32(v.w));
            *reinterpret_cast<float4*>(&As[r][acol]) = t;
        }
        #pragma unroll
        for (int p = 0; p < 4; p++) {
            int r = brow + p * 8;
            float4 v = *reinterpret_cast<const float4*>(
                B + (size_t)(kt + r) * N + colBase + bcol);
            float4 t;
            t.x = __uint_as_float(f2tf32(v.x));
            t.y = __uint_as_float(f2tf32(v.y));
            t.z = __uint_as_float(f2tf32(v.z));
            t.w = __uint_as_float(f2tf32(v.w));
            *reinterpret_cast<float4*>(&Bs[r][bcol]) = t;
        }
        __syncthreads();

        #pragma unroll
        for (int ks = 0; ks < 4; ks++) {
            const int kb = ks * 8;
            uint32_t af[4][4], bf[4][2];
            #pragma unroll
            for (int mt = 0; mt < 4; mt++) {
                int r = warpM * 64 + mt * 16;
                af[mt][0] = __float_as_uint(As[r + g    ][kb + tg    ]);
                af[mt][1] = __float_as_uint(As[r + g + 8][kb + tg    ]);
                af[mt][2] = __float_as_uint(As[r + g    ][kb + tg + 4]);
                af[mt][3] = __float_as_uint(As[r + g + 8][kb + tg + 4]);
            }
            #pragma unroll
            for (int nt = 0; nt < 4; nt++) {
                int cc = warpN * 32 + nt * 8 + g;
                bf[nt][0] = __float_as_uint(Bs[kb + tg    ][cc]);
                bf[nt][1] = __float_as_uint(Bs[kb + tg + 4][cc]);
            }
            #pragma unroll
            for (int mt = 0; mt < 4; mt++)
                #pragma unroll
                for (int nt = 0; nt < 4; nt++)
                    mma1688(c[mt][nt], af[mt][0], af[mt][1], af[mt][2], af[mt][3],
                            bf[nt][0], bf[nt][1]);
        }
        __syncthreads();
    }

    // epilogue
    #pragma unroll
    for (int mt = 0; mt < 4; mt++) {
        #pragma unroll
        for (int nt = 0; nt < 4; nt++) {
            int row = rowBase + warpM * 64 + mt * 16 + g;
            int col = colBase + warpN * 32 + nt * 8 + tg * 2;
            float2 v01 = make_float2(c[mt][nt][0], c[mt][nt][1]);
            float2 v23 = make_float2(c[mt][nt][2], c[mt][nt][3]);
            *reinterpret_cast<float2*>(C + (size_t)row * N + col)       = v01;
            *reinterpret_cast<float2*>(C + (size_t)(row + 8) * N + col) = v23;
        }
    }
}

// ---------------- RoPE + per-token GQA attention ---------------------------
// scores over heads at same position; repeat(k,4) => softmax over 32 with
// 4 identical copies per kv-head == softmax over the 8 kv-heads.
__global__ __launch_bounds__(256)
void attn_kernel()
{
    const int tok = blockIdx.x;
    const int pos = tok & (SEQ - 1);
    const int tid = threadIdx.x;

    __shared__ float qs[NHEADS][HD + 4];
    __shared__ float ks[NKV][HD + 4];
    __shared__ float vs[NKV][HD + 4];
    __shared__ float ps[NHEADS][NKV];

    const float* sp = g_sin + pos * 64;
    const float* cp = g_cos + pos * 64;

    // K/V load + RoPE(K)
    for (int idx = tid; idx < NKV * 64; idx += 256) {
        int j = idx >> 6, d = idx & 63;
        float s = sp[d], co = cp[d];
        const float* kptr = g_K + (size_t)tok * (NKV * HD) + j * HD;
        float k0 = kptr[d], k1 = kptr[d + 64];
        ks[j][d]      = k0 * co - k1 * s;
        ks[j][d + 64] = k1 * co + k0 * s;
        const float* vptr = g_V + (size_t)tok * (NKV * HD) + j * HD;
        vs[j][d]      = vptr[d];
        vs[j][d + 64] = vptr[d + 64];
    }
    // Q load + RoPE(Q)
    for (int idx = tid; idx < NHEADS * 64; idx += 256) {
        int h = idx >> 6, d = idx & 63;
        float s = sp[d], co = cp[d];
        const float* qptr = g_Q + (size_t)tok * HS + h * HD;
        float q0 = qptr[d], q1 = qptr[d + 64];
        qs[h][d]      = q0 * co - q1 * s;
        qs[h][d + 64] = q1 * co + q0 * s;
    }
    __syncthreads();

    // one (head, kv) score per thread
    const int h = tid >> 3, j = tid & 7;
    float acc = 0.f;
    #pragma unroll 8
    for (int d = 0; d < HD; d++) acc += qs[h][d] * ks[j][d];
    float sc = acc / sqrtf(128.0f);

    // softmax over j within 8-lane groups
    float m = sc;
    m = fmaxf(m, __shfl_xor_sync(0xffffffffu, m, 1));
    m = fmaxf(m, __shfl_xor_sync(0xffffffffu, m, 2));
    m = fmaxf(m, __shfl_xor_sync(0xffffffffu, m, 4));
    float e = expf(sc - m);
    float z = e;
    z += __shfl_xor_sync(0xffffffffu, z, 1);
    z += __shfl_xor_sync(0xffffffffu, z, 2);
    z += __shfl_xor_sync(0xffffffffu, z, 4);
    ps[h][j] = e / z;
    __syncthreads();

    // out[h][d] = sum_j p[h][j] * v[j][d]
    #pragma unroll
    for (int it = 0; it < 16; it++) {
        int idx = tid + it * 256;
        int hh = idx >> 7, d = idx & 127;
        float a = 0.f;
        #pragma unroll
        for (int jj = 0; jj < NKV; jj++) a += ps[hh][jj] * vs[jj][d];
        g_Y[(size_t)tok * HS + idx] = a;
    }
}

// ---------------- launch ---------------------------------------------------
extern "C" void kernel_launch(void* const* d_in, const int* in_sizes, int n_in,
                              void* d_out, int out_size)
{
    const float* hs = (const float*)d_in[0];
    const float* Wq = (const float*)d_in[1];
    const float* Wk = (const float*)d_in[2];
    const float* Wv = (const float*)d_in[3];
    const float* Wo = (const float*)d_in[4];
    float* out = (float*)d_out;

    float *qp, *kp, *vp, *yp;
    cudaGetSymbolAddress((void**)&qp, g_Q);
    cudaGetSymbolAddress((void**)&kp, g_K);
    cudaGetSymbolAddress((void**)&vp, g_V);
    cudaGetSymbolAddress((void**)&yp, g_Y);

    rope_table_kernel<<<SEQ, 64>>>();

    gemm_tf32<<<dim3(HS / BN, MTOT / BM), 256>>>(hs, Wq, qp, MTOT, HS, HS);
    gemm_tf32<<<dim3((NKV * HD) / BN, MTOT / BM), 256>>>(hs, Wk, kp, MTOT, NKV * HD, HS);
    gemm_tf32<<<dim3((NKV * HD) / BN, MTOT / BM), 256>>>(hs, Wv, vp, MTOT, NKV * HD, HS);

    attn_kernel<<<MTOT, 256>>>();

    gemm_tf32<<<dim3(HS / BN, MTOT / BM), 256>>>(yp, Wo, out, MTOT, HS, HS);
}

// round 3
// speedup vs baseline: 1.2484x; 1.2484x over previous
#include <cuda_runtime.h>
#include <cstdint>
#include <math.h>

// Problem constants
#define HSZ    4096
#define NHEADS 32
#define NKV    8
#define HD     128
#define SEQ    4096
#define BATCH  2
#define MTOT   (BATCH * SEQ)   // 8192
#define KD     4096            // GEMM K dim (both GEMMs)
#define NQKV   6144            // 4096 + 1024 + 1024

// ---------------- scratch (device globals) ---------------------------------
__device__ float g_Xr[(size_t)MTOT * HSZ];            // tf32-rounded hidden_states
__device__ float g_Wqkv[(size_t)KD * NQKV];           // [K][N] packed, rounded
__device__ float g_Wor[(size_t)KD * HSZ];             // rounded Wo [K][N]
__device__ float g_QKV[(size_t)MTOT * NQKV];          // q|k|v per token
__device__ float g_Y[(size_t)MTOT * HSZ];             // attn out (rounded)
__device__ float g_sin[SEQ * 64];
__device__ float g_cos[SEQ * 64];

// ---------------- helpers ---------------------------------------------------
__device__ __forceinline__ uint32_t f2tf32(float x) {
    uint32_t u;
    asm("cvt.rna.tf32.f32 %0, %1;" : "=r"(u) : "f"(x));
    return u;
}
__device__ __forceinline__ float rna(float x) { return __uint_as_float(f2tf32(x)); }

__device__ __forceinline__ uint32_t s2u(const void* p) {
    uint32_t a;
    asm("{ .reg .u64 t; cvta.to.shared.u64 t, %1; cvt.u32.u64 %0, t; }"
        : "=r"(a) : "l"(p));
    return a;
}
__device__ __forceinline__ void cpa16(uint32_t dst, const float* src) {
    asm volatile("cp.async.cg.shared.global [%0], [%1], 16;" :: "r"(dst), "l"(src) : "memory");
}
__device__ __forceinline__ void cpa_commit() {
    asm volatile("cp.async.commit_group;" ::: "memory");
}
template<int N_>
__device__ __forceinline__ void cpa_wait() {
    asm volatile("cp.async.wait_group %0;" :: "n"(N_) : "memory");
}

__device__ __forceinline__ void mma1688(float c[4],
                                        uint32_t a0, uint32_t a1, uint32_t a2, uint32_t a3,
                                        uint32_t b0, uint32_t b1) {
    asm("mma.sync.aligned.m16n8k8.row.col.f32.tf32.tf32.f32 "
        "{%0,%1,%2,%3}, {%4,%5,%6,%7}, {%8,%9}, {%0,%1,%2,%3};"
        : "+f"(c[0]), "+f"(c[1]), "+f"(c[2]), "+f"(c[3])
        : "r"(a0), "r"(a1), "r"(a2), "r"(a3), "r"(b0), "r"(b1));
}

// ---------------- RoPE table (verified) -------------------------------------
__global__ void rope_table_kernel() {
    int pos = blockIdx.x;
    int d   = threadIdx.x;            // 0..63
    int k2  = d & ~1;
    float e = (float)k2 / 64.0f;
    float emb  = (float)pow(10000.0, (double)e);
    float freq = (float)pos * emb;
    double fd = (double)freq;
    g_sin[pos * 64 + d] = (float)sin(fd);
    g_cos[pos * 64 + d] = (float)cos(fd);
}

// ---------------- prep kernels ----------------------------------------------
__global__ void round_copy_kernel(const float* __restrict__ src, float* __restrict__ dst, size_t n4) {
    size_t stride = (size_t)gridDim.x * blockDim.x;
    for (size_t i = (size_t)blockIdx.x * blockDim.x + threadIdx.x; i < n4; i += stride) {
        float4 v = reinterpret_cast<const float4*>(src)[i];
        v.x = rna(v.x); v.y = rna(v.y); v.z = rna(v.z); v.w = rna(v.w);
        reinterpret_cast<float4*>(dst)[i] = v;
    }
}

// pack [Wq | Wk | Wv] -> g_Wqkv [K][6144], tf32-rounded
__global__ void pack_qkv_kernel(const float* __restrict__ Wq,
                                const float* __restrict__ Wk,
                                const float* __restrict__ Wv) {
    const size_t total = (size_t)KD * NQKV / 4;
    size_t stride = (size_t)gridDim.x * blockDim.x;
    for (size_t i = (size_t)blockIdx.x * blockDim.x + threadIdx.x; i < total; i += stride) {
        int row = (int)(i / (NQKV / 4));
        int col = (int)(i % (NQKV / 4)) * 4;
        float4 v;
        if (col < 4096)
            v = *reinterpret_cast<const float4*>(Wq + (size_t)row * 4096 + col);
        else if (col < 5120)
            v = *reinterpret_cast<const float4*>(Wk + (size_t)row * 1024 + (col - 4096));
        else
            v = *reinterpret_cast<const float4*>(Wv + (size_t)row * 1024 + (col - 5120));
        v.x = rna(v.x); v.y = rna(v.y); v.z = rna(v.z); v.w = rna(v.w);
        *reinterpret_cast<float4*>(g_Wqkv + (size_t)row * NQKV + col) = v;
    }
}

// ---------------- pipelined TF32 GEMM ---------------------------------------
// C[M,N] = A[M,K] @ B[K,N]  (A,B pre-rounded to tf32 in gmem). K = 4096.
#define BM 128
#define BN 128
#define BK 32
#define STAGES 3
#define A_ELEMS (BM * (BK + 4))        // 4608 floats
#define B_ELEMS (BK * (BN + 8))        // 4352 floats
#define STAGE_FLOATS (A_ELEMS + B_ELEMS)   // 8960
#define STAGE_BYTES (STAGE_FLOATS * 4)     // 35840
#define GEMM_DYN (STAGES * STAGE_BYTES)    // 107520
#define NT (KD / BK)                   // 128

__global__ __launch_bounds__(256, 2)
void gemm_tf32(const float* __restrict__ A, const float* __restrict__ B,
               float* __restrict__ C, int N)
{
    extern __shared__ float dynf[];
    const uint32_t sbase = s2u(dynf);

    const int tid  = threadIdx.x;
    const int lane = tid & 31, warp = tid >> 5;
    const int warpM = warp & 1;
    const int warpN = warp >> 1;
    const int g  = lane >> 2;
    const int tg = lane & 3;

    // L2-friendly mapping: groups of 8 m-tiles across all n-tiles
    const int n_tiles = N / BN;
    const int per = 8 * n_tiles;
    const int gblk = blockIdx.x / per, rr0 = blockIdx.x % per;
    const int mt = gblk * 8 + (rr0 & 7);
    const int nt = rr0 >> 3;
    const int rowBase = mt * BM;
    const int colBase = nt * BN;

    const float* Ag = A + (size_t)rowBase * KD;

    // cp.async source/dest indices (per thread, 4 x 16B for A and B each)
    const int ar = tid >> 3;            // 0..31 (A row block, +32 per i)
    const int ac = (tid & 7) * 4;       // 0,4,..28
    const int br = tid >> 6;            // 0..3  (B row, +4 per i... see below)
    const int bc = (tid & 63) * 4;      // hmm

    float c[4][4][4];
    #pragma unroll
    for (int m2 = 0; m2 < 4; m2++)
        #pragma unroll
        for (int n2 = 0; n2 < 4; n2++)
            #pragma unroll
            for (int i = 0; i < 4; i++) c[m2][n2][i] = 0.f;

    // ---- load issuer: tile kt into stage buffer s
    auto issue = [&](int kt, int s) {
        const uint32_t sa = sbase + s * STAGE_BYTES;
        const uint32_t sb = sa + A_ELEMS * 4;
        // A: 128 rows x 32 floats
        #pragma unroll
        for (int i = 0; i < 4; i++) {
            int r = ar + i * 32;
            cpa16(sa + (r * (BK + 4) + ac) * 4,
                  Ag + (size_t)r * KD + kt * BK + ac);
        }
        // B: 32 rows x 128 floats
        #pragma unroll
        for (int i = 0; i < 4; i++) {
            int j = tid + i * 256;
            int r = j >> 5, cc = (j & 31) * 4;
            cpa16(sb + (r * (BN + 8) + cc) * 4,
                  B + (size_t)(kt * BK + r) * N + colBase + cc);
        }
    };

    // prologue: stages 0..STAGES-2
    #pragma unroll
    for (int s = 0; s < STAGES - 1; s++) { issue(s, s); cpa_commit(); }

    for (int kt = 0; kt < NT; kt++) {
        cpa_wait<STAGES - 2>();
        __syncthreads();

        // issue next tile into the stage just freed (computed last iter)
        if (kt + STAGES - 1 < NT) issue(kt + STAGES - 1, (kt + STAGES - 1) % STAGES);
        cpa_commit();

        const float* Asb = dynf + (kt % STAGES) * STAGE_FLOATS;
        const float* Bsb = Asb + A_ELEMS;

        #pragma unroll
        for (int ks = 0; ks < 4; ks++) {
            const int kb = ks * 8;
            uint32_t af[4][4], bf[4][2];
            #pragma unroll
            for (int m2 = 0; m2 < 4; m2++) {
                int r = warpM * 64 + m2 * 16;
                af[m2][0] = __float_as_uint(Asb[(r + g    ) * (BK + 4) + kb + tg    ]);
                af[m2][1] = __float_as_uint(Asb[(r + g + 8) * (BK + 4) + kb + tg    ]);
                af[m2][2] = __float_as_uint(Asb[(r + g    ) * (BK + 4) + kb + tg + 4]);
                af[m2][3] = __float_as_uint(Asb[(r + g + 8) * (BK + 4) + kb + tg + 4]);
            }
            #pragma unroll
            for (int n2 = 0; n2 < 4; n2++) {
                int cc = warpN * 32 + n2 * 8 + g;
                bf[n2][0] = __float_as_uint(Bsb[(kb + tg    ) * (BN + 8) + cc]);
                bf[n2][1] = __float_as_uint(Bsb[(kb + tg + 4) * (BN + 8) + cc]);
            }
            #pragma unroll
            for (int m2 = 0; m2 < 4; m2++)
                #pragma unroll
                for (int n2 = 0; n2 < 4; n2++)
                    mma1688(c[m2][n2], af[m2][0], af[m2][1], af[m2][2], af[m2][3],
                            bf[n2][0], bf[n2][1]);
        }
        __syncthreads();
    }

    // epilogue (verified round-1 pattern)
    #pragma unroll
    for (int m2 = 0; m2 < 4; m2++) {
        #pragma unroll
        for (int n2 = 0; n2 < 4; n2++) {
            int row = rowBase + warpM * 64 + m2 * 16 + g;
            int col = colBase + warpN * 32 + n2 * 8 + tg * 2;
            float2 v01 = make_float2(c[m2][n2][0], c[m2][n2][1]);
            float2 v23 = make_float2(c[m2][n2][2], c[m2][n2][3]);
            *reinterpret_cast<float2*>(C + (size_t)row * N + col)       = v01;
            *reinterpret_cast<float2*>(C + (size_t)(row + 8) * N + col) = v23;
        }
    }
}

// ---------------- RoPE + per-token GQA attention (verified) -----------------
__global__ __launch_bounds__(256)
void attn_kernel()
{
    const int tok = blockIdx.x;
    const int pos = tok & (SEQ - 1);
    const int tid = threadIdx.x;

    __shared__ float qs[NHEADS][HD + 4];
    __shared__ float ks[NKV][HD + 4];
    __shared__ float vs[NKV][HD + 4];
    __shared__ float ps[NHEADS][NKV];

    const float* sp = g_sin + pos * 64;
    const float* cp = g_cos + pos * 64;
    const float* base = g_QKV + (size_t)tok * NQKV;

    for (int idx = tid; idx < NKV * 64; idx += 256) {
        int j = idx >> 6, d = idx & 63;
        float s = sp[d], co = cp[d];
        const float* kptr = base + 4096 + j * HD;
        float k0 = kptr[d], k1 = kptr[d + 64];
        ks[j][d]      = k0 * co - k1 * s;
        ks[j][d + 64] = k1 * co + k0 * s;
        const float* vptr = base + 5120 + j * HD;
        vs[j][d]      = vptr[d];
        vs[j][d + 64] = vptr[d + 64];
    }
    for (int idx = tid; idx < NHEADS * 64; idx += 256) {
        int h = idx >> 6, d = idx & 63;
        float s = sp[d], co = cp[d];
        const float* qptr = base + h * HD;
        float q0 = qptr[d], q1 = qptr[d + 64];
        qs[h][d]      = q0 * co - q1 * s;
        qs[h][d + 64] = q1 * co + q0 * s;
    }
    __syncthreads();

    const int h = tid >> 3, j = tid & 7;
    float acc = 0.f;
    #pragma unroll 8
    for (int d = 0; d < HD; d++) acc += qs[h][d] * ks[j][d];
    float sc = acc / sqrtf(128.0f);

    float m = sc;
    m = fmaxf(m, __shfl_xor_sync(0xffffffffu, m, 1));
    m = fmaxf(m, __shfl_xor_sync(0xffffffffu, m, 2));
    m = fmaxf(m, __shfl_xor_sync(0xffffffffu, m, 4));
    float e = expf(sc - m);
    float z = e;
    z += __shfl_xor_sync(0xffffffffu, z, 1);
    z += __shfl_xor_sync(0xffffffffu, z, 2);
    z += __shfl_xor_sync(0xffffffffu, z, 4);
    ps[h][j] = e / z;
    __syncthreads();

    #pragma unroll
    for (int it = 0; it < 16; it++) {
        int idx = tid + it * 256;
        int hh = idx >> 7, d = idx & 127;
        float a = 0.f;
        #pragma unroll
        for (int jj = 0; jj < NKV; jj++) a += ps[hh][jj] * vs[jj][d];
        g_Y[(size_t)tok * HSZ + idx] = rna(a);   // rounded: feeds Wo GEMM
    }
}

// ---------------- launch ----------------------------------------------------
extern "C" void kernel_launch(void* const* d_in, const int* in_sizes, int n_in,
                              void* d_out, int out_size)
{
    const float* hs = (const float*)d_in[0];
    const float* Wq = (const float*)d_in[1];
    const float* Wk = (const float*)d_in[2];
    const float* Wv = (const float*)d_in[3];
    const float* Wo = (const float*)d_in[4];
    float* out = (float*)d_out;

    float *xr, *wqkv, *wor, *qkv, *yp;
    cudaGetSymbolAddress((void**)&xr,   g_Xr);
    cudaGetSymbolAddress((void**)&wqkv, g_Wqkv);
    cudaGetSymbolAddress((void**)&wor,  g_Wor);
    cudaGetSymbolAddress((void**)&qkv,  g_QKV);
    cudaGetSymbolAddress((void**)&yp,   g_Y);

    cudaFuncSetAttribute(gemm_tf32, cudaFuncAttributeMaxDynamicSharedMemorySize, GEMM_DYN);

    // prep
    round_copy_kernel<<<2048, 256>>>(hs, xr, (size_t)MTOT * HSZ / 4);
    round_copy_kernel<<<2048, 256>>>(Wo, wor, (size_t)KD * HSZ / 4);
    pack_qkv_kernel<<<2048, 256>>>(Wq, Wk, Wv);
    rope_table_kernel<<<SEQ, 64>>>();

    // fused QKV projection: [8192,4096] @ [4096,6144]
    gemm_tf32<<<(MTOT / BM) * (NQKV / BN), 256, GEMM_DYN>>>(xr, wqkv, qkv, NQKV);

    attn_kernel<<<MTOT, 256>>>();

    // output projection: [8192,4096] @ [4096,4096]
    gemm_tf32<<<(MTOT / BM) * (HSZ / BN), 256, GEMM_DYN>>>(yp, wor, out, HSZ);
}

// round 4
// speedup vs baseline: 2.4079x; 1.9288x over previous
#include <cuda_runtime.h>
#include <cuda_fp16.h>
#include <cstdint>
#include <math.h>

// Problem constants
#define HSZ    4096
#define NHEADS 32
#define NKV    8
#define HD     128
#define SEQ    4096
#define BATCH  2
#define MTOT   (BATCH * SEQ)   // 8192
#define KD     4096
#define NQKV   6144            // 4096 + 1024 + 1024

// ---------------- scratch (device globals) ---------------------------------
__device__ __half g_Xh[(size_t)MTOT * HSZ];     // fp16 hidden_states
__device__ __half g_Wqkvh[(size_t)KD * NQKV];   // packed [K][6144] fp16
__device__ __half g_Woh[(size_t)KD * HSZ];      // Wo fp16 [K][N]
__device__ float  g_QKV[(size_t)MTOT * NQKV];   // q|k|v per token (fp32)
__device__ __half g_Yh[(size_t)MTOT * HSZ];     // attn out fp16
__device__ float  g_sin[SEQ * 64];
__device__ float  g_cos[SEQ * 64];

// ---------------- helpers ---------------------------------------------------
__device__ __forceinline__ uint32_t s2u(const void* p) {
    uint32_t a;
    asm("{ .reg .u64 t; cvta.to.shared.u64 t, %1; cvt.u32.u64 %0, t; }"
        : "=r"(a) : "l"(p));
    return a;
}
__device__ __forceinline__ void cpa16(uint32_t dst, const void* src) {
    asm volatile("cp.async.cg.shared.global [%0], [%1], 16;" :: "r"(dst), "l"(src) : "memory");
}
__device__ __forceinline__ void cpa_commit() {
    asm volatile("cp.async.commit_group;" ::: "memory");
}
template<int N_>
__device__ __forceinline__ void cpa_wait() {
    asm volatile("cp.async.wait_group %0;" :: "n"(N_) : "memory");
}
__device__ __forceinline__ void ldmA(uint32_t r[4], uint32_t addr) {
    asm volatile("ldmatrix.sync.aligned.m8n8.x4.shared.b16 {%0,%1,%2,%3}, [%4];"
                 : "=r"(r[0]), "=r"(r[1]), "=r"(r[2]), "=r"(r[3]) : "r"(addr));
}
__device__ __forceinline__ void ldmB(uint32_t r[2], uint32_t addr) {
    asm volatile("ldmatrix.sync.aligned.m8n8.x2.trans.shared.b16 {%0,%1}, [%2];"
                 : "=r"(r[0]), "=r"(r[1]) : "r"(addr));
}
__device__ __forceinline__ void mma16816(float c[4], const uint32_t a[4], const uint32_t b[2]) {
    asm("mma.sync.aligned.m16n8k16.row.col.f32.f16.f16.f32 "
        "{%0,%1,%2,%3}, {%4,%5,%6,%7}, {%8,%9}, {%0,%1,%2,%3};"
        : "+f"(c[0]), "+f"(c[1]), "+f"(c[2]), "+f"(c[3])
        : "r"(a[0]), "r"(a[1]), "r"(a[2]), "r"(a[3]), "r"(b[0]), "r"(b[1]));
}

// ---------------- RoPE table (verified) -------------------------------------
__global__ void rope_table_kernel() {
    int pos = blockIdx.x;
    int d   = threadIdx.x;            // 0..63
    int k2  = d & ~1;
    float e = (float)k2 / 64.0f;
    float emb  = (float)pow(10000.0, (double)e);
    float freq = (float)pos * emb;
    double fd = (double)freq;
    g_sin[pos * 64 + d] = (float)sin(fd);
    g_cos[pos * 64 + d] = (float)cos(fd);
}

// ---------------- prep: fp32 -> fp16 conversions -----------------------------
__global__ void f2h_kernel(const float* __restrict__ src, __half* __restrict__ dst, size_t n4) {
    size_t stride = (size_t)gridDim.x * blockDim.x;
    for (size_t i = (size_t)blockIdx.x * blockDim.x + threadIdx.x; i < n4; i += stride) {
        float4 v = reinterpret_cast<const float4*>(src)[i];
        __half2 h0 = __floats2half2_rn(v.x, v.y);
        __half2 h1 = __floats2half2_rn(v.z, v.w);
        uint2 u;
        u.x = *reinterpret_cast<uint32_t*>(&h0);
        u.y = *reinterpret_cast<uint32_t*>(&h1);
        *reinterpret_cast<uint2*>(dst + i * 4) = u;
    }
}

// pack [Wq | Wk | Wv] -> g_Wqkvh [K][6144] fp16
__global__ void pack_qkv_kernel(const float* __restrict__ Wq,
                                const float* __restrict__ Wk,
                                const float* __restrict__ Wv) {
    const size_t total = (size_t)KD * NQKV / 4;
    size_t stride = (size_t)gridDim.x * blockDim.x;
    for (size_t i = (size_t)blockIdx.x * blockDim.x + threadIdx.x; i < total; i += stride) {
        int row = (int)(i / (NQKV / 4));
        int col = (int)(i % (NQKV / 4)) * 4;
        float4 v;
        if (col < 4096)
            v = *reinterpret_cast<const float4*>(Wq + (size_t)row * 4096 + col);
        else if (col < 5120)
            v = *reinterpret_cast<const float4*>(Wk + (size_t)row * 1024 + (col - 4096));
        else
            v = *reinterpret_cast<const float4*>(Wv + (size_t)row * 1024 + (col - 5120));
        __half2 h0 = __floats2half2_rn(v.x, v.y);
        __half2 h1 = __floats2half2_rn(v.z, v.w);
        uint2 u;
        u.x = *reinterpret_cast<uint32_t*>(&h0);
        u.y = *reinterpret_cast<uint32_t*>(&h1);
        *reinterpret_cast<uint2*>(g_Wqkvh + (size_t)row * NQKV + col) = u;
    }
}

// ---------------- pipelined FP16 GEMM (fp32 accumulate) ----------------------
// C[M,N] = A[M,K] @ B[K,N].  A,B fp16; K = 4096.
#define BM 128
#define BN 128
#define BK 64
#define STAGES 3
#define PA 72                          // A smem row pitch (halves): 64 + 8 pad
#define PB 136                         // B smem row pitch (halves): 128 + 8 pad
#define A_HALVES (BM * PA)             // 9216
#define B_HALVES (BK * PB)             // 8704
#define STAGE_HALVES (A_HALVES + B_HALVES)   // 17920
#define STAGE_BYTES (STAGE_HALVES * 2)       // 35840
#define GEMM_DYN (STAGES * STAGE_BYTES)      // 107520
#define NT (KD / BK)                   // 64

__global__ __launch_bounds__(256, 2)
void gemm_f16(const __half* __restrict__ A, const __half* __restrict__ B,
              float* __restrict__ C, int N)
{
    extern __shared__ __half dynh[];
    const uint32_t sbase = s2u(dynh);

    const int tid  = threadIdx.x;
    const int lane = tid & 31, warp = tid >> 5;
    const int warpM = warp & 1;        // 64-row slab
    const int warpN = warp >> 1;       // 32-col slab
    const int g  = lane >> 2;
    const int tg = lane & 3;

    // L2-friendly mapping: groups of 8 m-tiles across all n-tiles
    const int n_tiles = N / BN;
    const int per = 8 * n_tiles;
    const int gblk = blockIdx.x / per, rr0 = blockIdx.x % per;
    const int mt = gblk * 8 + (rr0 & 7);
    const int nt = rr0 >> 3;
    const int rowBase = mt * BM;
    const int colBase = nt * BN;

    const __half* Ag = A + (size_t)rowBase * KD;

    float c[4][4][4];
    #pragma unroll
    for (int m2 = 0; m2 < 4; m2++)
        #pragma unroll
        for (int n2 = 0; n2 < 4; n2++)
            #pragma unroll
            for (int i = 0; i < 4; i++) c[m2][n2][i] = 0.f;

    // ---- load issuer: K-tile kt -> stage s (256 thr x 8 x 16B)
    auto issue = [&](int kt, int s) {
        const uint32_t sa = sbase + s * STAGE_BYTES;
        const uint32_t sb = sa + A_HALVES * 2;
        #pragma unroll
        for (int i = 0; i < 4; i++) {          // A: 128 rows x 128B
            int ch = tid + i * 256;
            int r = ch >> 3, c8 = ch & 7;
            cpa16(sa + (r * PA + c8 * 8) * 2,
                  Ag + (size_t)r * KD + kt * BK + c8 * 8);
        }
        #pragma unroll
        for (int i = 0; i < 4; i++) {          // B: 64 rows x 256B
            int ch = tid + i * 256;
            int r = ch >> 4, c8 = ch & 15;
            cpa16(sb + (r * PB + c8 * 8) * 2,
                  B + (size_t)(kt * BK + r) * N + colBase + c8 * 8);
        }
    };

    #pragma unroll
    for (int s = 0; s < STAGES - 1; s++) { issue(s, s); cpa_commit(); }

    // ldmatrix base offsets (per lane)
    const uint32_t a_off = ((warpM * 64 + (lane & 15)) * PA + (lane >> 4) * 8) * 2;
    const uint32_t b_off = ((lane & 15) * PB + warpN * 32) * 2;

    for (int kt = 0; kt < NT; kt++) {
        cpa_wait<STAGES - 2>();
        __syncthreads();

        if (kt + STAGES - 1 < NT) issue(kt + STAGES - 1, (kt + STAGES - 1) % STAGES);
        cpa_commit();

        const uint32_t sa = sbase + (kt % STAGES) * STAGE_BYTES;
        const uint32_t sb = sa + A_HALVES * 2;

        #pragma unroll
        for (int ks = 0; ks < 4; ks++) {       // 4 x k16
            uint32_t af[4][4], bf[4][2];
            #pragma unroll
            for (int m2 = 0; m2 < 4; m2++)
                ldmA(af[m2], sa + a_off + (m2 * 16 * PA + ks * 16) * 2);
            #pragma unroll
            for (int n2 = 0; n2 < 4; n2++)
                ldmB(bf[n2], sb + b_off + (ks * 16 * PB + n2 * 8) * 2);
            #pragma unroll
            for (int m2 = 0; m2 < 4; m2++)
                #pragma unroll
                for (int n2 = 0; n2 < 4; n2++)
                    mma16816(c[m2][n2], af[m2], bf[n2]);
        }
        __syncthreads();
    }

    // epilogue (fp32 out)
    #pragma unroll
    for (int m2 = 0; m2 < 4; m2++) {
        #pragma unroll
        for (int n2 = 0; n2 < 4; n2++) {
            int row = rowBase + warpM * 64 + m2 * 16 + g;
            int col = colBase + warpN * 32 + n2 * 8 + tg * 2;
            float2 v01 = make_float2(c[m2][n2][0], c[m2][n2][1]);
            float2 v23 = make_float2(c[m2][n2][2], c[m2][n2][3]);
            *reinterpret_cast<float2*>(C + (size_t)row * N + col)       = v01;
            *reinterpret_cast<float2*>(C + (size_t)(row + 8) * N + col) = v23;
        }
    }
}

// ---------------- RoPE + per-token GQA attention (verified) -----------------
__global__ __launch_bounds__(256)
void attn_kernel()
{
    const int tok = blockIdx.x;
    const int pos = tok & (SEQ - 1);
    const int tid = threadIdx.x;

    __shared__ float qs[NHEADS][HD + 4];
    __shared__ float ks[NKV][HD + 4];
    __shared__ float vs[NKV][HD + 4];
    __shared__ float ps[NHEADS][NKV];

    const float* sp = g_sin + pos * 64;
    const float* cp = g_cos + pos * 64;
    const float* base = g_QKV + (size_t)tok * NQKV;

    for (int idx = tid; idx < NKV * 64; idx += 256) {
        int j = idx >> 6, d = idx & 63;
        float s = sp[d], co = cp[d];
        const float* kptr = base + 4096 + j * HD;
        float k0 = kptr[d], k1 = kptr[d + 64];
        ks[j][d]      = k0 * co - k1 * s;
        ks[j][d + 64] = k1 * co + k0 * s;
        const float* vptr = base + 5120 + j * HD;
        vs[j][d]      = vptr[d];
        vs[j][d + 64] = vptr[d + 64];
    }
    for (int idx = tid; idx < NHEADS * 64; idx += 256) {
        int h = idx >> 6, d = idx & 63;
        float s = sp[d], co = cp[d];
        const float* qptr = base + h * HD;
        float q0 = qptr[d], q1 = qptr[d + 64];
        qs[h][d]      = q0 * co - q1 * s;
        qs[h][d + 64] = q1 * co + q0 * s;
    }
    __syncthreads();

    const int h = tid >> 3, j = tid & 7;
    float acc = 0.f;
    #pragma unroll 8
    for (int d = 0; d < HD; d++) acc += qs[h][d] * ks[j][d];
    float sc = acc / sqrtf(128.0f);

    float m = sc;
    m = fmaxf(m, __shfl_xor_sync(0xffffffffu, m, 1));
    m = fmaxf(m, __shfl_xor_sync(0xffffffffu, m, 2));
    m = fmaxf(m, __shfl_xor_sync(0xffffffffu, m, 4));
    float e = expf(sc - m);
    float z = e;
    z += __shfl_xor_sync(0xffffffffu, z, 1);
    z += __shfl_xor_sync(0xffffffffu, z, 2);
    z += __shfl_xor_sync(0xffffffffu, z, 4);
    ps[h][j] = e / z;
    __syncthreads();

    #pragma unroll
    for (int it = 0; it < 16; it++) {
        int idx = tid + it * 256;
        int hh = idx >> 7, d = idx & 127;
        float a = 0.f;
        #pragma unroll
        for (int jj = 0; jj < NKV; jj++) a += ps[hh][jj] * vs[jj][d];
        g_Yh[(size_t)tok * HSZ + idx] = __float2half_rn(a);   // feeds Wo GEMM
    }
}

// ---------------- launch ----------------------------------------------------
extern "C" void kernel_launch(void* const* d_in, const int* in_sizes, int n_in,
                              void* d_out, int out_size)
{
    const float* hs = (const float*)d_in[0];
    const float* Wq = (const float*)d_in[1];
    const float* Wk = (const float*)d_in[2];
    const float* Wv = (const float*)d_in[3];
    const float* Wo = (const float*)d_in[4];
    float* out = (float*)d_out;

    __half *xh, *wqkvh, *woh, *yh;
    float *qkv;
    cudaGetSymbolAddress((void**)&xh,    g_Xh);
    cudaGetSymbolAddress((void**)&wqkvh, g_Wqkvh);
    cudaGetSymbolAddress((void**)&woh,   g_Woh);
    cudaGetSymbolAddress((void**)&qkv,   g_QKV);
    cudaGetSymbolAddress((void**)&yh,    g_Yh);

    cudaFuncSetAttribute(gemm_f16, cudaFuncAttributeMaxDynamicSharedMemorySize, GEMM_DYN);

    // prep
    f2h_kernel<<<2048, 256>>>(hs, xh, (size_t)MTOT * HSZ / 4);
    f2h_kernel<<<2048, 256>>>(Wo, woh, (size_t)KD * HSZ / 4);
    pack_qkv_kernel<<<2048, 256>>>(Wq, Wk, Wv);
    rope_table_kernel<<<SEQ, 64>>>();

    // fused QKV projection: [8192,4096] @ [4096,6144]
    gemm_f16<<<(MTOT / BM) * (NQKV / BN), 256, GEMM_DYN>>>(xh, wqkvh, qkv, NQKV);

    attn_kernel<<<MTOT, 256>>>();

    // output projection: [8192,4096] @ [4096,4096]
    gemm_f16<<<(MTOT / BM) * (HSZ / BN), 256, GEMM_DYN>>>(yh, woh, out, HSZ);
}